// round 2
// baseline (speedup 1.0000x reference)
#include <cuda_runtime.h>
#include <cstddef>

#define N_NODES 50000
#define DIN 96
#define DOUT 256

// Scratch (allocation-free rule: __device__ globals)
__device__ float g_agg[(size_t)N_NODES * DIN];    // 19.2 MB
__device__ float g_h[(size_t)N_NODES * DOUT];     // 51.2 MB

// ---------------------------------------------------------------------------
// agg = eps * x   (GIN residual folded into the SpMM accumulator init)
// ---------------------------------------------------------------------------
__global__ void init_agg_kernel(const float* __restrict__ x,
                                const float* __restrict__ eps, int n4) {
    int i = blockIdx.x * blockDim.x + threadIdx.x;
    if (i < n4) {
        float e = eps[0];
        float4 v = ((const float4*)x)[i];
        v.x *= e; v.y *= e; v.z *= e; v.w *= e;
        ((float4*)g_agg)[i] = v;
    }
}

// ---------------------------------------------------------------------------
// agg[dst] += vals[e] * x[src]  via vectorized L2 reductions (red.v4.f32)
// ---------------------------------------------------------------------------
__global__ void spmm_kernel(const float* __restrict__ x,
                            const int* __restrict__ src,
                            const int* __restrict__ dst,
                            const float* __restrict__ vals, int total) {
    int idx = blockIdx.x * blockDim.x + threadIdx.x;
    if (idx >= total) return;
    int e = idx / 24;
    int c = idx - e * 24;
    int s = src[e];
    int d = dst[e];
    float v = vals[e];
    float4 xv = *(const float4*)(x + (size_t)s * DIN + c * 4);
    float* p = g_agg + (size_t)d * DIN + c * 4;
    asm volatile("red.global.add.v4.f32 [%0], {%1,%2,%3,%4};"
                 :: "l"(p), "f"(v * xv.x), "f"(v * xv.y),
                    "f"(v * xv.z), "f"(v * xv.w)
                 : "memory");
}

// ---------------------------------------------------------------------------
// Tiled SGEMM with packed f32x2 FMA: C[M,256] = A[M,K] @ B[K,256].
// BM=BN=128, BK=32, 256 threads, 8x8 microtile held as 8x4 packed f32x2.
// Optional fused inference-BN + ReLU epilogue.
// ---------------------------------------------------------------------------
template <bool FUSE_BN>
__global__ void __launch_bounds__(256)
gemm_kernel(const float* __restrict__ A, const float* __restrict__ B,
            float* __restrict__ C, int M, int K,
            const float* __restrict__ gamma, const float* __restrict__ beta,
            const float* __restrict__ mean, const float* __restrict__ var) {
    __shared__ float As[32][132];
    __shared__ float Bs[32][128];

    const int tid = threadIdx.x;
    const int rowBlock = blockIdx.y * 128;
    const int colBlock = blockIdx.x * 128;

    // acc[i][jp] packs columns (2*jp, 2*jp+1) as f32x2
    unsigned long long accp[8][4];
#pragma unroll
    for (int i = 0; i < 8; i++)
#pragma unroll
        for (int j = 0; j < 4; j++) accp[i][j] = 0ull;

    const int rg = (tid >> 4) * 8;
    const int cg = (tid & 15) * 8;

    for (int k0 = 0; k0 < K; k0 += 32) {
        // Load A tile [128 rows x 32 k], store transposed As[k][row]
#pragma unroll
        for (int i = 0; i < 4; i++) {
            int f = tid + i * 256;
            int r = f >> 3;
            int kq = f & 7;
            int grow = rowBlock + r;
            float4 v = make_float4(0.f, 0.f, 0.f, 0.f);
            if (grow < M)
                v = *(const float4*)(A + (size_t)grow * K + (k0 + kq * 4));
            As[kq * 4 + 0][r] = v.x;
            As[kq * 4 + 1][r] = v.y;
            As[kq * 4 + 2][r] = v.z;
            As[kq * 4 + 3][r] = v.w;
        }
        // Load B tile [32 k x 128 cols]
#pragma unroll
        for (int i = 0; i < 4; i++) {
            int f = tid + i * 256;
            int kr = f >> 5;
            int cq = f & 31;
            *(float4*)&Bs[kr][cq * 4] =
                *(const float4*)(B + (size_t)(k0 + kr) * DOUT + colBlock + cq * 4);
        }
        __syncthreads();

#pragma unroll 8
        for (int k = 0; k < 32; k++) {
            float a[8];
            *(float4*)(a)     = *(const float4*)&As[k][rg];
            *(float4*)(a + 4) = *(const float4*)&As[k][rg + 4];
            float4 b0 = *(const float4*)&Bs[k][cg];
            float4 b1 = *(const float4*)&Bs[k][cg + 4];
            unsigned long long bp[4];
            asm("mov.b64 %0, {%1, %2};" : "=l"(bp[0]) : "f"(b0.x), "f"(b0.y));
            asm("mov.b64 %0, {%1, %2};" : "=l"(bp[1]) : "f"(b0.z), "f"(b0.w));
            asm("mov.b64 %0, {%1, %2};" : "=l"(bp[2]) : "f"(b1.x), "f"(b1.y));
            asm("mov.b64 %0, {%1, %2};" : "=l"(bp[3]) : "f"(b1.z), "f"(b1.w));
#pragma unroll
            for (int i = 0; i < 8; i++) {
                unsigned long long ap;
                asm("mov.b64 %0, {%1, %1};" : "=l"(ap) : "f"(a[i]));
#pragma unroll
                for (int j = 0; j < 4; j++)
                    asm("fma.rn.f32x2 %0, %1, %2, %0;"
                        : "+l"(accp[i][j]) : "l"(ap), "l"(bp[j]));
            }
        }
        __syncthreads();
    }

    // Unpack accumulators
    float acc[8][8];
#pragma unroll
    for (int i = 0; i < 8; i++)
#pragma unroll
        for (int j = 0; j < 4; j++)
            asm("mov.b64 {%0, %1}, %2;"
                : "=f"(acc[i][2 * j]), "=f"(acc[i][2 * j + 1]) : "l"(accp[i][j]));

    // Epilogue (optionally fused inference-BN + ReLU)
    float sc[8], bi[8];
    if (FUSE_BN) {
#pragma unroll
        for (int j = 0; j < 8; j++) {
            int col = colBlock + cg + j;
            float s = gamma[col] * rsqrtf(var[col] + 1e-3f);
            sc[j] = s;
            bi[j] = beta[col] - mean[col] * s;
        }
    }
#pragma unroll
    for (int i = 0; i < 8; i++) {
        int grow = rowBlock + rg + i;
        if (grow < M) {
            float out[8];
#pragma unroll
            for (int j = 0; j < 8; j++) {
                float v = acc[i][j];
                if (FUSE_BN) v = fmaxf(fmaf(v, sc[j], bi[j]), 0.f);
                out[j] = v;
            }
            float* cp = C + (size_t)grow * DOUT + colBlock + cg;
            *(float4*)cp       = *(float4*)out;
            *(float4*)(cp + 4) = *(float4*)(out + 4);
        }
    }
}

// ---------------------------------------------------------------------------
extern "C" void kernel_launch(void* const* d_in, const int* in_sizes, int n_in,
                              void* d_out, int out_size) {
    const float* x     = (const float*)d_in[0];
    const int*   src   = (const int*)d_in[1];
    const int*   dst   = (const int*)d_in[2];
    const float* vals  = (const float*)d_in[3];
    const float* eps   = (const float*)d_in[4];
    const float* W0    = (const float*)d_in[5];
    const float* W1    = (const float*)d_in[6];
    const float* gamma = (const float*)d_in[7];
    const float* beta  = (const float*)d_in[8];
    const float* mean  = (const float*)d_in[9];
    const float* var   = (const float*)d_in[10];

    int N = in_sizes[0] / DIN;
    int E = in_sizes[1];

    float *agg, *h;
    cudaGetSymbolAddress((void**)&agg, g_agg);
    cudaGetSymbolAddress((void**)&h, g_h);

    // 1. agg = eps * x
    int n4 = N * (DIN / 4);
    init_agg_kernel<<<(n4 + 255) / 256, 256>>>(x, eps, n4);

    // 2. scatter-add edge messages
    int total = E * (DIN / 4);
    spmm_kernel<<<(total + 255) / 256, 256>>>(x, src, dst, vals, total);

    // 3. h = relu(bn(agg @ W0))
    dim3 grid(DOUT / 128, (N + 127) / 128);
    gemm_kernel<true><<<grid, 256>>>(agg, W0, h, N, DIN, gamma, beta, mean, var);

    // 4. out = h @ W1
    gemm_kernel<false><<<grid, 256>>>(h, W1, (float*)d_out, N, DOUT,
                                      nullptr, nullptr, nullptr, nullptr);
}

// round 4
// speedup vs baseline: 1.4162x; 1.4162x over previous
#include <cuda_runtime.h>
#include <cuda_bf16.h>
#include <cstdint>
#include <cstddef>

#define NMAX 50000
#define DIN 96
#define DOUT 256

// ---------------- scratch (__device__ globals; no allocs allowed) ----------
__device__ float g_agg[(size_t)NMAX * DIN];
__device__ __nv_bfloat16 g_aext0[(size_t)NMAX * (2 * DIN)];    // [N][192] = [hi96|lo96]
__device__ __nv_bfloat16 g_hext[(size_t)NMAX * (2 * DOUT)];    // [N][512] = [hi256|lo256]
__device__ __nv_bfloat16 g_b0ext[DOUT * (3 * DIN)];            // [256][288] = [hi|hi|lo]
__device__ __nv_bfloat16 g_b1ext[DOUT * (3 * DOUT)];           // [256][768] = [hi|hi|lo]

// ---------------- helpers ---------------------------------------------------
__device__ __forceinline__ uint32_t smem_u32(const void* p) {
    uint32_t a;
    asm("{ .reg .u64 t; cvta.to.shared.u64 t, %1; cvt.u32.u64 %0, t; }"
        : "=r"(a) : "l"(p));
    return a;
}
__device__ __forceinline__ void ldsm4(uint32_t* r, uint32_t addr) {
    asm volatile("ldmatrix.sync.aligned.m8n8.x4.shared.b16 {%0,%1,%2,%3}, [%4];"
                 : "=r"(r[0]), "=r"(r[1]), "=r"(r[2]), "=r"(r[3]) : "r"(addr));
}
__device__ __forceinline__ void mma16816(float* c, const uint32_t* a, const uint32_t* b) {
    asm volatile(
        "mma.sync.aligned.m16n8k16.row.col.f32.bf16.bf16.f32 "
        "{%0,%1,%2,%3}, {%4,%5,%6,%7}, {%8,%9}, {%0,%1,%2,%3};"
        : "+f"(c[0]), "+f"(c[1]), "+f"(c[2]), "+f"(c[3])
        : "r"(a[0]), "r"(a[1]), "r"(a[2]), "r"(a[3]), "r"(b[0]), "r"(b[1]));
}
__device__ __forceinline__ uint32_t split_pack_hi(float v0, float v1,
                                                  uint32_t& lo_out) {
    __nv_bfloat16 h0 = __float2bfloat16(v0);
    __nv_bfloat16 h1 = __float2bfloat16(v1);
    __nv_bfloat16 l0 = __float2bfloat16(v0 - __bfloat162float(h0));
    __nv_bfloat16 l1 = __float2bfloat16(v1 - __bfloat162float(h1));
    __nv_bfloat162 hp; hp.x = h0; hp.y = h1;
    __nv_bfloat162 lp; lp.x = l0; lp.y = l1;
    lo_out = *(uint32_t*)&lp;
    return *(uint32_t*)&hp;
}

// ---------------------------------------------------------------------------
// agg = eps * x
// ---------------------------------------------------------------------------
__global__ void init_agg_kernel(const float* __restrict__ x,
                                const float* __restrict__ eps, int n4) {
    int i = blockIdx.x * blockDim.x + threadIdx.x;
    if (i < n4) {
        float e = eps[0];
        float4 v = ((const float4*)x)[i];
        v.x *= e; v.y *= e; v.z *= e; v.w *= e;
        ((float4*)g_agg)[i] = v;
    }
}

// ---------------------------------------------------------------------------
// agg[dst] += vals[e] * x[src] via red.global.add.v4.f32
// ---------------------------------------------------------------------------
__global__ void spmm_kernel(const float* __restrict__ x,
                            const int* __restrict__ src,
                            const int* __restrict__ dst,
                            const float* __restrict__ vals, int total) {
    int idx = blockIdx.x * blockDim.x + threadIdx.x;
    if (idx >= total) return;
    int e = idx / 24;
    int c = idx - e * 24;
    int s = src[e];
    int d = dst[e];
    float v = vals[e];
    float4 xv = *(const float4*)(x + (size_t)s * DIN + c * 4);
    float* p = g_agg + (size_t)d * DIN + c * 4;
    asm volatile("red.global.add.v4.f32 [%0], {%1,%2,%3,%4};"
                 :: "l"(p), "f"(v * xv.x), "f"(v * xv.y),
                    "f"(v * xv.z), "f"(v * xv.w) : "memory");
}

// ---------------------------------------------------------------------------
// agg fp32 [N][96] -> aext0 bf16 [N][192] = [hi|lo]
// ---------------------------------------------------------------------------
__global__ void split_agg_kernel(const float* __restrict__ src,
                                 __nv_bfloat16* __restrict__ dstp, int n) {
    int i = blockIdx.x * blockDim.x + threadIdx.x;
    if (i < n) {
        int row = i / DIN, k = i - row * DIN;
        float v = src[i];
        __nv_bfloat16 h = __float2bfloat16(v);
        dstp[(size_t)row * (2 * DIN) + k] = h;
        dstp[(size_t)row * (2 * DIN) + DIN + k] =
            __float2bfloat16(v - __bfloat162float(h));
    }
}

// W fp32 [K][256] -> Bext bf16 [256][3K] = [hi|hi|lo] transposed
__global__ void wsplit_kernel(const float* __restrict__ W,
                              __nv_bfloat16* __restrict__ Bext, int K) {
    int i = blockIdx.x * blockDim.x + threadIdx.x;
    if (i < K * DOUT) {
        int k = i / DOUT, n = i - k * DOUT;
        float v = W[i];
        __nv_bfloat16 h = __float2bfloat16(v);
        __nv_bfloat16 l = __float2bfloat16(v - __bfloat162float(h));
        size_t base = (size_t)n * (3 * K);
        Bext[base + k] = h;
        Bext[base + K + k] = h;
        Bext[base + 2 * K + k] = l;
    }
}

// ---------------------------------------------------------------------------
// bf16 HMMA GEMM with extended K (error-split encoded in K dimension).
//   C[M,256] tile 128x128, 8 warps (4x2), warp tile 32x64, mma m16n8k16.
//   A: [M][WRAP] bf16, logical K' = KP with wrap: ksrc = k' >= WRAP ? k'-WRAP : k'
//   B: [256][KP] bf16 (n-major, k contiguous)
//   MODE 0: BN+ReLU epilogue, write Cext [M][2*DOUT] = [hi|lo]
//   MODE 1: plain epilogue, write fp32 Cf [M][256]
// ---------------------------------------------------------------------------
#define STG_BYTES (128 * 80)

template <int MODE, int KP, int WRAP>
__global__ void __launch_bounds__(256)
gemm_mma(const __nv_bfloat16* __restrict__ Aext,
         const __nv_bfloat16* __restrict__ Bext,
         float* __restrict__ Cf, __nv_bfloat16* __restrict__ Cext, int M,
         const float* __restrict__ gamma, const float* __restrict__ beta,
         const float* __restrict__ mean, const float* __restrict__ var) {
    __shared__ __align__(16) unsigned char sA[2][STG_BYTES];
    __shared__ __align__(16) unsigned char sB[2][STG_BYTES];
    __shared__ float s_sc[128], s_bi[128];

    const int tid = threadIdx.x;
    const int wid = tid >> 5, lane = tid & 31;
    const int mBlock = blockIdx.y * 128, nBlock = blockIdx.x * 128;
    const int wm = wid & 3, wn = wid >> 2;
    const int tq = lane >> 2, tr = lane & 3;

    const uint32_t aBase = smem_u32(sA);
    const uint32_t bBase = smem_u32(sB);

    // loader: 2 chunks x (A,B) per thread per stage
    const int ldrow = tid >> 2;
    const int ldkc = tid & 3;

    // ldmatrix per-lane offsets
    const int arow = ((lane >> 3) & 1) * 8 + (lane & 7);
    const int akb = (lane >> 4) * 8;               // 0 or 8 (k elems)
    const int brow = ((lane >> 4) & 1) * 8 + (lane & 7);
    const int bkb = ((lane >> 3) & 1) * 8;
    const uint32_t aAddr0 = aBase + (uint32_t)(wm * 32 + arow) * 80 + akb * 2;
    const uint32_t bAddr0 = bBase + (uint32_t)(wn * 64 + brow) * 80 + bkb * 2;

    float acc[2][8][4];
#pragma unroll
    for (int i = 0; i < 2; i++)
#pragma unroll
        for (int j = 0; j < 8; j++)
#pragma unroll
            for (int q = 0; q < 4; q++) acc[i][j][q] = 0.f;

    constexpr int NS = KP / 32;

    auto issue = [&](int ks, int stage) {
        const int k0 = ks * 32;
        const int ksA = (k0 >= WRAP) ? k0 - WRAP : k0;
#pragma unroll
        for (int i = 0; i < 2; i++) {
            int row = ldrow + i * 64;
            uint32_t sa = aBase + stage * STG_BYTES + row * 80 + ldkc * 16;
            const void* ga = Aext + (size_t)(mBlock + row) * WRAP + ksA + ldkc * 8;
            int sz = (mBlock + row < M) ? 16 : 0;
            asm volatile("cp.async.cg.shared.global [%0], [%1], 16, %2;"
                         :: "r"(sa), "l"(ga), "r"(sz) : "memory");
            uint32_t sb = bBase + stage * STG_BYTES + row * 80 + ldkc * 16;
            const void* gb = Bext + (size_t)(nBlock + row) * KP + k0 + ldkc * 8;
            asm volatile("cp.async.cg.shared.global [%0], [%1], 16;"
                         :: "r"(sb), "l"(gb) : "memory");
        }
        asm volatile("cp.async.commit_group;" ::: "memory");
    };

    issue(0, 0);

    for (int ks = 0; ks < NS; ks++) {
        const int st = ks & 1;
        if (ks + 1 < NS) {
            issue(ks + 1, st ^ 1);
            asm volatile("cp.async.wait_group 1;" ::: "memory");
        } else {
            asm volatile("cp.async.wait_group 0;" ::: "memory");
        }
        __syncthreads();

        const uint32_t aS = aAddr0 + st * STG_BYTES;
        const uint32_t bS = bAddr0 + st * STG_BYTES;
#pragma unroll
        for (int ksub = 0; ksub < 2; ksub++) {
            uint32_t a[2][4];
#pragma unroll
            for (int mt = 0; mt < 2; mt++)
                ldsm4(a[mt], aS + mt * (16 * 80) + ksub * 32);
            uint32_t b[8][2];
#pragma unroll
            for (int np = 0; np < 4; np++) {
                uint32_t t[4];
                ldsm4(t, bS + np * (16 * 80) + ksub * 32);
                b[2 * np][0] = t[0]; b[2 * np][1] = t[1];
                b[2 * np + 1][0] = t[2]; b[2 * np + 1][1] = t[3];
            }
#pragma unroll
            for (int mt = 0; mt < 2; mt++)
#pragma unroll
                for (int nt = 0; nt < 8; nt++)
                    mma16816(acc[mt][nt], a[mt], b[nt]);
        }
        __syncthreads();
    }

    // BN coefficient precompute
    if (MODE == 0) {
        if (tid < 128) {
            int col = nBlock + tid;
            float s = gamma[col] * rsqrtf(var[col] + 1e-3f);
            s_sc[tid] = s;
            s_bi[tid] = beta[col] - mean[col] * s;
        }
        __syncthreads();
    }

    // epilogue
#pragma unroll
    for (int mt = 0; mt < 2; mt++) {
        const int m0 = mBlock + wm * 32 + mt * 16 + tq;
#pragma unroll
        for (int nt = 0; nt < 8; nt++) {
            const int cloc = wn * 64 + nt * 8 + 2 * tr;
            const int col = nBlock + cloc;
            float* c = acc[mt][nt];
            if (MODE == 0) {
                float s0 = s_sc[cloc], s1 = s_sc[cloc + 1];
                float b0 = s_bi[cloc], b1 = s_bi[cloc + 1];
                if (m0 < M) {
                    float v0 = fmaxf(fmaf(c[0], s0, b0), 0.f);
                    float v1 = fmaxf(fmaf(c[1], s1, b1), 0.f);
                    uint32_t lo, hi = split_pack_hi(v0, v1, lo);
                    size_t base = (size_t)m0 * (2 * DOUT) + col;
                    *(uint32_t*)(Cext + base) = hi;
                    *(uint32_t*)(Cext + base + DOUT) = lo;
                }
                if (m0 + 8 < M) {
                    float v0 = fmaxf(fmaf(c[2], s0, b0), 0.f);
                    float v1 = fmaxf(fmaf(c[3], s1, b1), 0.f);
                    uint32_t lo, hi = split_pack_hi(v0, v1, lo);
                    size_t base = (size_t)(m0 + 8) * (2 * DOUT) + col;
                    *(uint32_t*)(Cext + base) = hi;
                    *(uint32_t*)(Cext + base + DOUT) = lo;
                }
            } else {
                if (m0 < M)
                    *(float2*)(Cf + (size_t)m0 * DOUT + col) =
                        make_float2(c[0], c[1]);
                if (m0 + 8 < M)
                    *(float2*)(Cf + (size_t)(m0 + 8) * DOUT + col) =
                        make_float2(c[2], c[3]);
            }
        }
    }
}

// ---------------------------------------------------------------------------
extern "C" void kernel_launch(void* const* d_in, const int* in_sizes, int n_in,
                              void* d_out, int out_size) {
    const float* x     = (const float*)d_in[0];
    const int*   src   = (const int*)d_in[1];
    const int*   dst   = (const int*)d_in[2];
    const float* vals  = (const float*)d_in[3];
    const float* eps   = (const float*)d_in[4];
    const float* W0    = (const float*)d_in[5];
    const float* W1    = (const float*)d_in[6];
    const float* gamma = (const float*)d_in[7];
    const float* beta  = (const float*)d_in[8];
    const float* mean  = (const float*)d_in[9];
    const float* var   = (const float*)d_in[10];

    int N = in_sizes[0] / DIN;
    int E = in_sizes[1];

    float* agg;            cudaGetSymbolAddress((void**)&agg, g_agg);
    __nv_bfloat16 *aext0, *hext, *b0ext, *b1ext;
    cudaGetSymbolAddress((void**)&aext0, g_aext0);
    cudaGetSymbolAddress((void**)&hext, g_hext);
    cudaGetSymbolAddress((void**)&b0ext, g_b0ext);
    cudaGetSymbolAddress((void**)&b1ext, g_b1ext);

    // weight transpose + split (tiny, independent)
    wsplit_kernel<<<(DIN * DOUT + 255) / 256, 256>>>(W0, b0ext, DIN);
    wsplit_kernel<<<(DOUT * DOUT + 255) / 256, 256>>>(W1, b1ext, DOUT);

    // 1. agg = eps * x
    int n4 = N * (DIN / 4);
    init_agg_kernel<<<(n4 + 255) / 256, 256>>>(x, eps, n4);

    // 2. scatter-add edge messages
    int total = E * (DIN / 4);
    spmm_kernel<<<(total + 255) / 256, 256>>>(x, src, dst, vals, total);

    // 3. split agg -> bf16 [hi|lo]
    int nel = N * DIN;
    split_agg_kernel<<<(nel + 255) / 256, 256>>>(agg, aext0, nel);

    // 4. h(hi|lo) = relu(bn(agg @ W0))   (K' = 288, wrap 192)
    dim3 grid(DOUT / 128, (N + 127) / 128);
    gemm_mma<0, 3 * DIN, 2 * DIN><<<grid, 256>>>(
        aext0, b0ext, nullptr, hext, N, gamma, beta, mean, var);

    // 5. out = h @ W1                    (K' = 768, wrap 512)
    gemm_mma<1, 3 * DOUT, 2 * DOUT><<<grid, 256>>>(
        hext, b1ext, (float*)d_out, nullptr, N,
        nullptr, nullptr, nullptr, nullptr);
}